// round 12
// baseline (speedup 1.0000x reference)
#include <cuda_runtime.h>
#include <cstdint>

// Single persistent kernel, 256 co-resident blocks x 512 threads:
//   phase A (8 items/block):  conv 4x4/s4 -> gate; 32nd-arriver block per
//                             batch runs exact K-th-largest radix select and
//                             releases d_ready[b]
//   phase B (24 items/block): out = in * (gate >= thr ? gate : 0),
//                             4x upsample, 3ch bcast, MLP=4, sector skip.
// All cross-block waits are on flags set by co-resident blocks (grid=256 <=
// 2 blocks/SM * 148 SMs guaranteed by __launch_bounds__(512,2)) -> no deadlock.
__device__ float    d_gate[64 * 16384];
__device__ unsigned d_thr[64];
__device__ int      d_count[64];   // conv arrivals per batch (selector resets)
__device__ int      d_ready[64];   // threshold ready flag (last block resets)
__device__ int      d_done;        // finished blocks (last block resets)

__device__ __forceinline__ unsigned f2key(float f) {
    unsigned u = __float_as_uint(f);
    return (u & 0x80000000u) ? ~u : (u | 0x80000000u);  // monotone float->uint
}

__global__ void __launch_bounds__(512, 2) gate_persistent_kernel(
        const float4* __restrict__ in, const float* __restrict__ wk,
        float4* __restrict__ out) {
    __shared__ float4 w[12];
    __shared__ unsigned hist[16][256];
    __shared__ int cnt[256];
    __shared__ unsigned s_prefix;
    __shared__ int s_k;
    __shared__ int s_rank;
    __shared__ unsigned s_thr;
    __shared__ int s_last;

    const int t = threadIdx.x;
    const int bid = blockIdx.x;
    const int warp = t >> 5;
    const int lane = t & 31;

    if (t < 12) w[t] = reinterpret_cast<const float4*>(wk)[t];
    __syncthreads();

    // ===================== phase A: conv (+ fused select) =====================
    // 2048 conv items; block bid takes items bid + 256*i  (batch-interleaved:
    // batch group g fully written after iteration ~g/8).
#pragma unroll 1
    for (int i = 0; i < 8; i++) {
        const int item = bid + 256 * i;          // [0, 2048)
        const int b = item >> 5;                 // batch
        const int pix = (item & 31) * 512 + t;   // [0,16384) gate pixel
        const int x = pix & 127;
        const int y = pix >> 7;

        const float4* base = in + (size_t)b * 196608 + x;
        float sum = 0.0f;
#pragma unroll
        for (int c = 0; c < 3; c++) {
#pragma unroll
            for (int r = 0; r < 4; r++) {
                float4 v = base[c * 65536 + (4 * y + r) * 128];
                float4 ww = w[c * 4 + r];
                sum += v.x * ww.x + v.y * ww.y + v.z * ww.z + v.w * ww.w;
            }
        }
        d_gate[b * 16384 + pix] = sum;

        // release our stores, then count arrival for this batch
        __threadfence();
        __syncthreads();
        if (t == 0) s_rank = atomicAdd(&d_count[b], 1);
        __syncthreads();

        if (s_rank == 31) {
            // -------- select for batch b (keys reloaded from L2 per pass) ----
            const float4* g4 =
                reinterpret_cast<const float4*>(d_gate + b * 16384);
            if (t == 0) { s_prefix = 0u; s_k = 4096; }

#pragma unroll
            for (int pass = 0; pass < 4; pass++) {
                const int shift = 24 - 8 * pass;
#pragma unroll
                for (int z = t; z < 16 * 256; z += 512)
                    (&hist[0][0])[z] = 0u;
                __syncthreads();

                const unsigned pmask =
                    pass ? (0xFFFFFFFFu << (32 - 8 * pass)) : 0u;
                const unsigned prefix = s_prefix;
                const int kcur = s_k;

#pragma unroll
                for (int z = 0; z < 8; z++) {
                    float4 v = g4[t + z * 512];
                    unsigned k4[4] = { f2key(v.x), f2key(v.y),
                                       f2key(v.z), f2key(v.w) };
#pragma unroll
                    for (int j = 0; j < 4; j++) {
                        unsigned u = k4[j];
                        unsigned bn = ((u & pmask) == prefix)
                                          ? ((u >> shift) & 0xFFu)
                                          : 0xFFFFFFFFu;
                        unsigned same = __match_any_sync(0xFFFFFFFFu, bn);
                        if (bn != 0xFFFFFFFFu && lane == (__ffs(same) - 1))
                            hist[warp][bn] += __popc(same);
                    }
                }
                __syncthreads();

                if (t < 256) {
                    int c = 0;
#pragma unroll
                    for (int wg = 0; wg < 16; wg++) c += hist[wg][t];
                    cnt[t] = c;
                }
                __syncthreads();

                if (warp == 0) {
                    int v[8], s[8];
#pragma unroll
                    for (int j = 0; j < 8; j++) v[j] = cnt[lane * 8 + j];
                    s[7] = v[7];
#pragma unroll
                    for (int j = 6; j >= 0; j--) s[j] = s[j + 1] + v[j];
                    int suf = s[0];
#pragma unroll
                    for (int off = 1; off < 32; off <<= 1) {
                        int o = __shfl_down_sync(0xFFFFFFFFu, suf, off);
                        if (lane + off < 32) suf += o;
                    }
                    int above = suf - s[0];
#pragma unroll
                    for (int j = 0; j < 8; j++) {
                        int Sj = s[j] + above;
                        int Sn = (j < 7 ? s[j + 1] : 0) + above;
                        if (Sj >= kcur && Sn < kcur) {
                            s_prefix =
                                prefix | ((unsigned)(lane * 8 + j) << shift);
                            s_k = kcur - Sn;
                        }
                    }
                }
                __syncthreads();
            }

            if (t == 0) {
                d_thr[b] = s_prefix;                 // exact K-th largest key
                d_count[b] = 0;                      // replay-safe reset
                __threadfence();                     // release thr before flag
                atomicExch(&d_ready[b], 1);
            }
            __syncthreads();
        }
    }

    // ============================ phase B: mul ================================
    // 6144 items; block bid takes items bid + 256*i (batches ascending).
    // Item: batch b = item/96; r = item%96; channel c = r>>5; slice s = r&31.
    // Thread handles 1 gate cell x 4 image rows (MLP=4, R7 shape).
#pragma unroll 1
    for (int i = 0; i < 24; i++) {
        const int item = bid + 256 * i;          // [0, 6144)
        const int b = item / 96;
        const int r = item - 96 * b;
        const int c = r >> 5;

        if (t == 0) {
            while (atomicAdd(&d_ready[b], 0) == 0) __nanosleep(128);
            s_thr = atomicAdd(&d_thr[b], 0u);    // L2 read: no stale L1 line
        }
        __syncthreads();
        const unsigned thr = s_thr;

        const int idx = (r & 31) * 512 + t;      // [0,16384) gate cell
        const int gy = idx >> 7;
        const int x4 = idx & 127;

        float gv = d_gate[b * 16384 + idx];
        bool alive = f2key(gv) >= thr;

        size_t base =
            (size_t)(b * 3 + c) * 65536 + (size_t)(4 * gy) * 128 + x4;

        float4 z = make_float4(0.f, 0.f, 0.f, 0.f);
        float4 v0 = z, v1 = z, v2 = z, v3 = z;
        if (alive) {
            float4 t0 = in[base];
            float4 t1 = in[base + 128];
            float4 t2 = in[base + 256];
            float4 t3 = in[base + 384];
            v0.x = t0.x * gv; v0.y = t0.y * gv; v0.z = t0.z * gv; v0.w = t0.w * gv;
            v1.x = t1.x * gv; v1.y = t1.y * gv; v1.z = t1.z * gv; v1.w = t1.w * gv;
            v2.x = t2.x * gv; v2.y = t2.y * gv; v2.z = t2.z * gv; v2.w = t2.w * gv;
            v3.x = t3.x * gv; v3.y = t3.y * gv; v3.z = t3.z * gv; v3.w = t3.w * gv;
        }
        out[base]       = v0;
        out[base + 128] = v1;
        out[base + 256] = v2;
        out[base + 384] = v3;
        __syncthreads();   // s_thr reuse safety
    }

    // ====================== replay-safe flag teardown ========================
    if (t == 0) s_last = (atomicAdd(&d_done, 1) == 255);
    __syncthreads();
    if (s_last) {
        if (t < 64) d_ready[t] = 0;
        __syncthreads();
        __threadfence();
        if (t == 0) atomicExch(&d_done, 0);
    }
}

// ---------------------------------------------------------------------------
extern "C" void kernel_launch(void* const* d_in, const int* in_sizes, int n_in,
                              void* d_out, int out_size) {
    const float* inp = (const float*)d_in[0];
    const float* wk  = (const float*)d_in[1];
    if (n_in >= 2 && in_sizes[0] == 48) {  // defensive: swap if order flipped
        inp = (const float*)d_in[1];
        wk  = (const float*)d_in[0];
    }

    gate_persistent_kernel<<<256, 512>>>((const float4*)inp, wk,
                                         (float4*)d_out);
}

// round 13
// speedup vs baseline: 2.0512x; 2.0512x over previous
#include <cuda_runtime.h>
#include <cstdint>

// Gate pipeline (2 kernels):
//   K1: conv 4x4/s4 [64,3,512,512] -> gate[64,128,128]   (R7, proven 33us)
//   K2: 64 select blocks (bids 0..63, wave-1 resident, no dependencies)
//       + 12288 mul blocks that one-shot spin on d_ready[batch].
//       Select: exact K-th-largest radix key, warp-private histograms.
//       Mul: R7 shape — 1 gate cell x 4 rows, MLP=4, sector-exact skip.
__device__ float    d_gate[64 * 16384];
__device__ unsigned d_thr[64];
__device__ int      d_ready[64];   // set by select block; reset by last mul blk
__device__ int      d_mdone[64];   // mul blocks finished per batch (replay-safe)

__device__ __forceinline__ unsigned f2key(float f) {
    unsigned u = __float_as_uint(f);
    return (u & 0x80000000u) ? ~u : (u | 0x80000000u);  // monotone float->uint
}

// ---------------------------------------------------------------------------
// K1: conv. One thread per gate pixel, 12 coalesced float4 loads. 80% DRAM.
// ---------------------------------------------------------------------------
__global__ void gate_conv_kernel(const float4* __restrict__ in,
                                 const float* __restrict__ wk) {
    __shared__ float4 w[12];
    int t = threadIdx.x;
    if (t < 12) w[t] = reinterpret_cast<const float4*>(wk)[t];
    __syncthreads();

    int idx = blockIdx.x * blockDim.x + t;      // [0, 64*16384)
    int x = idx & 127;
    int y = (idx >> 7) & 127;
    int b = idx >> 14;

    const float4* base = in + (size_t)b * 196608 + x;
    float sum = 0.0f;
#pragma unroll
    for (int c = 0; c < 3; c++) {
#pragma unroll
        for (int i = 0; i < 4; i++) {
            float4 v = base[c * 65536 + (4 * y + i) * 128];
            float4 ww = w[c * 4 + i];
            sum += v.x * ww.x + v.y * ww.y + v.z * ww.z + v.w * ww.w;
        }
    }
    d_gate[idx] = sum;
}

// ---------------------------------------------------------------------------
// K2: fused select + mul. All blocks 256 threads.
//   bid <  64 : select for batch bid (keys reloaded from L2 per pass;
//               warp-private match_any histograms; single-warp suffix scan)
//   bid >= 64 : mul item (192 per batch), one-shot spin on d_ready[b].
// ---------------------------------------------------------------------------
__global__ void __launch_bounds__(256) gate_selmul_kernel(
        const float4* __restrict__ in, float4* __restrict__ out) {
    const int t = threadIdx.x;
    const int bid = blockIdx.x;

    if (bid < 64) {
        // ======================= select block ================================
        __shared__ unsigned hist[8][256];
        __shared__ int cnt[256];
        __shared__ unsigned s_prefix;
        __shared__ int s_k;

        const int b = bid;
        const int warp = t >> 5;
        const int lane = t & 31;
        const float4* g4 = reinterpret_cast<const float4*>(d_gate + b * 16384);

        if (t == 0) { s_prefix = 0u; s_k = 4096; }

#pragma unroll
        for (int pass = 0; pass < 4; pass++) {
            const int shift = 24 - 8 * pass;
#pragma unroll
            for (int z = t; z < 8 * 256; z += 256)
                (&hist[0][0])[z] = 0u;
            __syncthreads();

            const unsigned pmask = pass ? (0xFFFFFFFFu << (32 - 8 * pass)) : 0u;
            const unsigned prefix = s_prefix;
            const int kcur = s_k;

            // 16 float4 (64 keys) per thread, reloaded from L2 each pass
#pragma unroll
            for (int i = 0; i < 16; i++) {
                float4 v = g4[t + i * 256];
                unsigned k4[4] = { f2key(v.x), f2key(v.y),
                                   f2key(v.z), f2key(v.w) };
#pragma unroll
                for (int j = 0; j < 4; j++) {
                    unsigned u = k4[j];
                    unsigned bn = ((u & pmask) == prefix)
                                      ? ((u >> shift) & 0xFFu) : 0xFFFFFFFFu;
                    unsigned same = __match_any_sync(0xFFFFFFFFu, bn);
                    if (bn != 0xFFFFFFFFu && lane == (__ffs(same) - 1))
                        hist[warp][bn] += __popc(same);   // warp-private
                }
            }
            __syncthreads();

            {
                int c = 0;
#pragma unroll
                for (int wg = 0; wg < 8; wg++) c += hist[wg][t];
                cnt[t] = c;
            }
            __syncthreads();

            if (warp == 0) {
                int v[8], s[8];
#pragma unroll
                for (int j = 0; j < 8; j++) v[j] = cnt[lane * 8 + j];
                s[7] = v[7];
#pragma unroll
                for (int j = 6; j >= 0; j--) s[j] = s[j + 1] + v[j];
                int suf = s[0];
#pragma unroll
                for (int off = 1; off < 32; off <<= 1) {
                    int o = __shfl_down_sync(0xFFFFFFFFu, suf, off);
                    if (lane + off < 32) suf += o;
                }
                int above = suf - s[0];
#pragma unroll
                for (int j = 0; j < 8; j++) {
                    int Sj = s[j] + above;
                    int Sn = (j < 7 ? s[j + 1] : 0) + above;
                    if (Sj >= kcur && Sn < kcur) {
                        s_prefix = prefix | ((unsigned)(lane * 8 + j) << shift);
                        s_k = kcur - Sn;
                    }
                }
            }
            __syncthreads();
        }

        if (t == 0) {
            d_thr[b] = s_prefix;           // exact key of K-th largest
            __threadfence();               // publish thr before the flag
            atomicExch(&d_ready[b], 1);    // release
        }
        return;
    }

    // =========================== mul block ==================================
    __shared__ unsigned s_thr;

    const int item = bid - 64;             // [0, 12288)
    const int b = item / 192;              // batch
    const int r = item - 192 * b;
    const int c = r >> 6;                  // channel 0..2
    const int blk = r & 63;                // slice within (b,c)

    if (t == 0) {
        while (atomicAdd(&d_ready[b], 0) == 0) __nanosleep(64);
        s_thr = atomicAdd(&d_thr[b], 0u);  // L2 read: dodge stale-L1 hazard
    }
    __syncthreads();
    const unsigned thr = s_thr;

    const int idx = blk * 256 + t;         // [0,16384) gate cell
    const int gy = idx >> 7;
    const int x4 = idx & 127;

    float gv = d_gate[b * 16384 + idx];
    bool alive = f2key(gv) >= thr;

    size_t base = (size_t)(b * 3 + c) * 65536 + (size_t)(4 * gy) * 128 + x4;

    float4 z = make_float4(0.f, 0.f, 0.f, 0.f);
    float4 v0 = z, v1 = z, v2 = z, v3 = z;
    if (alive) {
        float4 t0 = in[base];
        float4 t1 = in[base + 128];
        float4 t2 = in[base + 256];
        float4 t3 = in[base + 384];
        v0.x = t0.x * gv; v0.y = t0.y * gv; v0.z = t0.z * gv; v0.w = t0.w * gv;
        v1.x = t1.x * gv; v1.y = t1.y * gv; v1.z = t1.z * gv; v1.w = t1.w * gv;
        v2.x = t2.x * gv; v2.y = t2.y * gv; v2.z = t2.z * gv; v2.w = t2.w * gv;
        v3.x = t3.x * gv; v3.y = t3.y * gv; v3.z = t3.z * gv; v3.w = t3.w * gv;
    }
    out[base]       = v0;
    out[base + 128] = v1;
    out[base + 256] = v2;
    out[base + 384] = v3;

    // replay-safe teardown: 192nd-finishing mul block of this batch resets
    __syncthreads();
    if (t == 0) {
        int n = atomicAdd(&d_mdone[b], 1);
        if (n == 191) {
            d_ready[b] = 0;
            d_mdone[b] = 0;
            __threadfence();
        }
    }
}

// ---------------------------------------------------------------------------
extern "C" void kernel_launch(void* const* d_in, const int* in_sizes, int n_in,
                              void* d_out, int out_size) {
    const float* inp = (const float*)d_in[0];
    const float* wk  = (const float*)d_in[1];
    if (n_in >= 2 && in_sizes[0] == 48) {  // defensive: swap if order flipped
        inp = (const float*)d_in[1];
        wk  = (const float*)d_in[0];
    }

    gate_conv_kernel<<<4096, 256>>>((const float4*)inp, wk);
    // 64 select blocks + 64*3*64 mul blocks
    gate_selmul_kernel<<<64 + 12288, 256>>>((const float4*)inp,
                                            (float4*)d_out);
}

// round 14
// speedup vs baseline: 2.1810x; 1.0633x over previous
#include <cuda_runtime.h>
#include <cstdint>

// Gate pipeline, 3 kernels chained with Programmatic Dependent Launch:
//   K1 conv:   4x4/s4 [64,3,512,512] -> gate[64,128,128]   (~33us, BW floor)
//   K2 select: per-batch exact K-th-largest key, 64x1024, register keys
//   K3 mul:    out = in * (gate >= thr ? gate : 0), R7 shape (MLP=4, skip)
// PDL: consumers launch during producer drain; cudaGridDependencySynchronize
// guarantees producer-grid completion (and store visibility) before use.
__device__ float    d_gate[64 * 16384];
__device__ unsigned d_thr[64];

__device__ __forceinline__ unsigned f2key(float f) {
    unsigned u = __float_as_uint(f);
    return (u & 0x80000000u) ? ~u : (u | 0x80000000u);  // monotone float->uint
}

// ---------------------------------------------------------------------------
// K1: conv. One thread per gate pixel, 12 coalesced float4 loads.
// ---------------------------------------------------------------------------
__global__ void gate_conv_kernel(const float4* __restrict__ in,
                                 const float* __restrict__ wk) {
    __shared__ float4 w[12];
    int t = threadIdx.x;
    if (t < 12) w[t] = reinterpret_cast<const float4*>(wk)[t];
    __syncthreads();

    int idx = blockIdx.x * blockDim.x + t;      // [0, 64*16384)
    int x = idx & 127;
    int y = (idx >> 7) & 127;
    int b = idx >> 14;

    const float4* base = in + (size_t)b * 196608 + x;
    float sum = 0.0f;
#pragma unroll
    for (int c = 0; c < 3; c++) {
#pragma unroll
        for (int i = 0; i < 4; i++) {
            float4 v = base[c * 65536 + (4 * y + i) * 128];
            float4 ww = w[c * 4 + i];
            sum += v.x * ww.x + v.y * ww.y + v.z * ww.z + v.w * ww.w;
        }
    }
    d_gate[idx] = sum;

#if __CUDA_ARCH__ >= 900
    cudaTriggerProgrammaticLaunchCompletion();   // let K2 start filling SMs
#endif
}

// ---------------------------------------------------------------------------
// K2: per-batch K-th-largest key, MSB-first radix select, 4x8-bit.
// 64 blocks x 1024 threads: 16 register keys/thread -> serial match_any
// chain halved vs 512-thread version. Warp-private histograms (no atomics),
// single-warp shfl suffix scan.
// ---------------------------------------------------------------------------
__global__ void __launch_bounds__(1024) gate_select_kernel() {
    __shared__ unsigned hist[32][256];   // per-warp private, 32KB
    __shared__ int cnt[256];
    __shared__ unsigned s_prefix;
    __shared__ int s_k;

    const int row = blockIdx.x;
    const int t = threadIdx.x;          // blockDim = 1024
    const int warp = t >> 5;
    const int lane = t & 31;

#if __CUDA_ARCH__ >= 900
    cudaGridDependencySynchronize();     // wait for conv grid completion
#endif

    // one-shot vectorized key load: 4 float4 = 16 keys per thread
    unsigned key[16];
    const float4* g4 = reinterpret_cast<const float4*>(d_gate + row * 16384);
#pragma unroll
    for (int i = 0; i < 4; i++) {
        float4 v = g4[t + i * 1024];
        key[4 * i + 0] = f2key(v.x);
        key[4 * i + 1] = f2key(v.y);
        key[4 * i + 2] = f2key(v.z);
        key[4 * i + 3] = f2key(v.w);
    }

    if (t == 0) { s_prefix = 0u; s_k = 4096; }

#pragma unroll
    for (int pass = 0; pass < 4; pass++) {
        const int shift = 24 - 8 * pass;
#pragma unroll
        for (int i = t; i < 32 * 256; i += 1024)
            (&hist[0][0])[i] = 0u;
        __syncthreads();

        const unsigned pmask = pass ? (0xFFFFFFFFu << (32 - 8 * pass)) : 0u;
        const unsigned prefix = s_prefix;
        const int kcur = s_k;

#pragma unroll
        for (int i = 0; i < 16; i++) {
            unsigned u = key[i];
            unsigned bn = ((u & pmask) == prefix) ? ((u >> shift) & 0xFFu)
                                                  : 0xFFFFFFFFu;
            unsigned same = __match_any_sync(0xFFFFFFFFu, bn);
            if (bn != 0xFFFFFFFFu && lane == (__ffs(same) - 1))
                hist[warp][bn] += __popc(same);      // warp-private
        }
        __syncthreads();

        if (t < 256) {
            int c = 0;
#pragma unroll
            for (int wg = 0; wg < 32; wg++) c += hist[wg][t];
            cnt[t] = c;
        }
        __syncthreads();

        // warp 0: suffix scan over 256 bins (8 bins/lane) + pick bin
        if (warp == 0) {
            int v[8], s[8];
#pragma unroll
            for (int j = 0; j < 8; j++) v[j] = cnt[lane * 8 + j];
            s[7] = v[7];
#pragma unroll
            for (int j = 6; j >= 0; j--) s[j] = s[j + 1] + v[j];
            int suf = s[0];
#pragma unroll
            for (int off = 1; off < 32; off <<= 1) {
                int o = __shfl_down_sync(0xFFFFFFFFu, suf, off);
                if (lane + off < 32) suf += o;
            }
            int above = suf - s[0];
#pragma unroll
            for (int j = 0; j < 8; j++) {
                int Sj = s[j] + above;
                int Sn = (j < 7 ? s[j + 1] : 0) + above;
                if (Sj >= kcur && Sn < kcur) {
                    s_prefix = prefix | ((unsigned)(lane * 8 + j) << shift);
                    s_k = kcur - Sn;
                }
            }
        }
        __syncthreads();
    }

    if (t == 0) d_thr[row] = s_prefix;   // exact key of K-th largest

#if __CUDA_ARCH__ >= 900
    cudaTriggerProgrammaticLaunchCompletion();   // let K3 start filling SMs
#endif
}

// ---------------------------------------------------------------------------
// K3: out = in * gate. One thread = one gate cell x 4 image rows:
// 1 gate load, 4 independent in loads (MLP=4, predicated off when dead),
// 4 stores. Warp per-instruction access = contiguous 512B. (R7 shape.)
// ---------------------------------------------------------------------------
__global__ void gate_mul_kernel(const float4* __restrict__ in,
                                float4* __restrict__ out) {
    int i  = blockIdx.x * blockDim.x + threadIdx.x;  // [0, 128*128)
    int x4 = i & 127;              // float4 col == gate col
    int gy = i >> 7;               // gate row
    int c  = blockIdx.y;           // channel
    int b  = blockIdx.z;           // batch

#if __CUDA_ARCH__ >= 900
    cudaGridDependencySynchronize();     // wait for select grid completion
#endif

    unsigned thr = __ldg(&d_thr[b]);
    float gv = d_gate[b * 16384 + gy * 128 + x4];
    bool alive = f2key(gv) >= thr;

    size_t base = (size_t)(b * 3 + c) * 65536 + (size_t)(4 * gy) * 128 + x4;

    float4 z = make_float4(0.f, 0.f, 0.f, 0.f);
    float4 v0 = z, v1 = z, v2 = z, v3 = z;
    if (alive) {
        float4 t0 = in[base];
        float4 t1 = in[base + 128];
        float4 t2 = in[base + 256];
        float4 t3 = in[base + 384];
        v0.x = t0.x * gv; v0.y = t0.y * gv; v0.z = t0.z * gv; v0.w = t0.w * gv;
        v1.x = t1.x * gv; v1.y = t1.y * gv; v1.z = t1.z * gv; v1.w = t1.w * gv;
        v2.x = t2.x * gv; v2.y = t2.y * gv; v2.z = t2.z * gv; v2.w = t2.w * gv;
        v3.x = t3.x * gv; v3.y = t3.y * gv; v3.z = t3.z * gv; v3.w = t3.w * gv;
    }
    out[base]       = v0;
    out[base + 128] = v1;
    out[base + 256] = v2;
    out[base + 384] = v3;
}

// ---------------------------------------------------------------------------
extern "C" void kernel_launch(void* const* d_in, const int* in_sizes, int n_in,
                              void* d_out, int out_size) {
    const float* inp = (const float*)d_in[0];
    const float* wk  = (const float*)d_in[1];
    if (n_in >= 2 && in_sizes[0] == 48) {  // defensive: swap if order flipped
        inp = (const float*)d_in[1];
        wk  = (const float*)d_in[0];
    }

    gate_conv_kernel<<<4096, 256>>>((const float4*)inp, wk);

    // K2 with PDL (fallback to plain launch if the attribute is rejected)
    {
        cudaLaunchConfig_t cfg = {};
        cfg.gridDim = dim3(64);
        cfg.blockDim = dim3(1024);
        cudaLaunchAttribute at[1];
        at[0].id = cudaLaunchAttributeProgrammaticStreamSerialization;
        at[0].val.programmaticStreamSerializationAllowed = 1;
        cfg.attrs = at;
        cfg.numAttrs = 1;
        if (cudaLaunchKernelEx(&cfg, gate_select_kernel) != cudaSuccess)
            gate_select_kernel<<<64, 1024>>>();
    }

    // K3 with PDL
    {
        cudaLaunchConfig_t cfg = {};
        cfg.gridDim = dim3(64, 3, 64);
        cfg.blockDim = dim3(256);
        cudaLaunchAttribute at[1];
        at[0].id = cudaLaunchAttributeProgrammaticStreamSerialization;
        at[0].val.programmaticStreamSerializationAllowed = 1;
        cfg.attrs = at;
        cfg.numAttrs = 1;
        if (cudaLaunchKernelEx(&cfg, gate_mul_kernel,
                               (const float4*)inp, (float4*)d_out)
            != cudaSuccess) {
            dim3 mgrid(64, 3, 64);
            gate_mul_kernel<<<mgrid, 256>>>((const float4*)inp,
                                            (float4*)d_out);
        }
    }
}